// round 14
// baseline (speedup 1.0000x reference)
#include <cuda_runtime.h>
#include <cuda_bf16.h>
#include <cstdint>

#define N_NODES 8192
#define F_IN    200
#define F_OUT   100
#define NPAD    128
#define KSPLIT  2
#define RSPLIT  32

// ---------------- scratch (no allocations allowed) ----------------
__device__ __align__(16) float g_colsum_part[RSPLIT * N_NODES];
__device__ __align__(16) float g_colsum[N_NODES];
__device__ __align__(16) float g_Wt[F_IN * NPAD];                        // [F_IN][NPAD]
__device__ __align__(16) float g_G [(size_t)N_NODES * NPAD];             // diag(dinv) h0 W^T (fp32)
__device__ __align__(16) __nv_bfloat16 g_Gt[(size_t)NPAD * N_NODES];     // bf16, [n][k]
__device__ __align__(16) __nv_bfloat16 g_Abf[(size_t)N_NODES * N_NODES]; // bf16 copy of A
__device__ __align__(16) float g_P [(size_t)KSPLIT * N_NODES * NPAD];    // split-K partials

// ================= helpers =================
__device__ __forceinline__ uint32_t smem_u32(const void* p) {
    uint32_t a;
    asm("{ .reg .u64 t; cvta.to.shared.u64 t, %1; cvt.u32.u64 %0, t; }" : "=r"(a) : "l"(p));
    return a;
}
__device__ __forceinline__ void cp16(uint32_t s, const void* g) {
    asm volatile("cp.async.cg.shared.global [%0], [%1], 16;" :: "r"(s), "l"(g) : "memory");
}
// pack two fp32 -> bf16x2 (lo = first/lower-k element), round-to-nearest
__device__ __forceinline__ uint32_t pack_bf16x2(float lo, float hi) {
    uint32_t r;
    asm("cvt.rn.bf16x2.f32 %0, %1, %2;" : "=r"(r) : "f"(hi), "f"(lo));
    return r;
}

// ------- 1) column sums of A + fused bf16 conversion of A (one 256MB read) -------
__global__ void colsum_cvt_kernel(const float* __restrict__ A) {
    int j4 = blockIdx.x * 256 + threadIdx.x;          // float4 column index 0..2047
    int i0 = blockIdx.y * (N_NODES / RSPLIT);
    const float4* p = (const float4*)(A + (size_t)i0 * N_NODES) + j4;
    __nv_bfloat16* dst = g_Abf + (size_t)i0 * N_NODES + j4 * 4;
    float4 s = make_float4(0.f, 0.f, 0.f, 0.f);
    #pragma unroll 4
    for (int i = 0; i < N_NODES / RSPLIT; i++) {
        float4 v = p[(size_t)i * (N_NODES / 4)];
        s.x += v.x; s.y += v.y; s.z += v.z; s.w += v.w;
        uint2 w;
        w.x = pack_bf16x2(v.x, v.y);
        w.y = pack_bf16x2(v.z, v.w);
        *(uint2*)(dst + (size_t)i * N_NODES) = w;
    }
    *(float4*)&g_colsum_part[blockIdx.y * N_NODES + j4 * 4] = s;
}
__global__ void colsum_fin_kernel() {
    int j = blockIdx.x * 256 + threadIdx.x;
    float s = 1.0f;
    #pragma unroll
    for (int p = 0; p < RSPLIT; p++) s += g_colsum_part[p * N_NODES + j];
    g_colsum[j] = s;
}

// ---------------- 2) W -> Wt (zero-padded to NPAD cols) ----------------
__global__ void wt_kernel(const float* __restrict__ W) {
    int idx = blockIdx.x * 256 + threadIdx.x;
    if (idx < F_IN * NPAD) {
        int f = idx >> 7, o = idx & 127;
        g_Wt[idx] = (o < F_OUT) ? W[o * F_IN + f] : 0.f;
    }
}

// ------- 3) G = diag(dinv) h0 @ Wt, fused transpose-to-bf16 (writes G and Gt) ----
// 64 rows/CTA (grid 128), 512 threads (16 warps -> 4 rows/warp).
#define G_ROWS    64
#define G_THREADS 512
#define G_SMEM    ((F_IN * NPAD + G_ROWS * F_IN) * 4)   // 153600 B
__global__ __launch_bounds__(G_THREADS, 1) void g_kernel(const float* __restrict__ h0) {
    extern __shared__ float gsm[];
    float* Wts = gsm;                       // [F_IN][NPAD]
    float* h0s = gsm + F_IN * NPAD;         // [G_ROWS][F_IN]
    const int t = threadIdx.x, warp = t >> 5, lane = t & 31;
    const int row0 = blockIdx.x * G_ROWS;

    for (int q = t; q < F_IN * NPAD / 4; q += G_THREADS)
        *(float4*)&Wts[q * 4] = *(const float4*)&g_Wt[q * 4];
    for (int q = t; q < G_ROWS * F_IN / 4; q += G_THREADS)
        *(float4*)&h0s[q * 4] = *(const float4*)&h0[(size_t)row0 * F_IN + q * 4];
    __syncthreads();

    unsigned long long acc2[4][2];
    #pragma unroll
    for (int r = 0; r < 4; r++) { acc2[r][0] = 0ull; acc2[r][1] = 0ull; }
    const float* hrow = h0s + (warp * 4) * F_IN;

    #pragma unroll 4
    for (int k = 0; k < F_IN; k++) {
        ulonglong2 b2 = *(const ulonglong2*)&Wts[k * NPAD + lane * 4];
        #pragma unroll
        for (int r = 0; r < 4; r++) {
            unsigned int av = __float_as_uint(hrow[r * F_IN + k]);
            unsigned long long a2;
            asm("mov.b64 %0, {%1, %1};" : "=l"(a2) : "r"(av));
            asm("fma.rn.f32x2 %0, %1, %2, %0;" : "+l"(acc2[r][0]) : "l"(a2), "l"(b2.x));
            asm("fma.rn.f32x2 %0, %1, %2, %0;" : "+l"(acc2[r][1]) : "l"(a2), "l"(b2.y));
        }
    }
    float vr[4][4];
    #pragma unroll
    for (int r = 0; r < 4; r++) {
        int row = row0 + warp * 4 + r;
        float dj = rsqrtf(g_colsum[row]);
        unsigned int l0, h0_, l1, h1;
        asm("mov.b64 {%0, %1}, %2;" : "=r"(l0), "=r"(h0_) : "l"(acc2[r][0]));
        asm("mov.b64 {%0, %1}, %2;" : "=r"(l1), "=r"(h1)  : "l"(acc2[r][1]));
        vr[r][0] = __uint_as_float(l0) * dj;  vr[r][1] = __uint_as_float(h0_) * dj;
        vr[r][2] = __uint_as_float(l1) * dj;  vr[r][3] = __uint_as_float(h1) * dj;
        *(float4*)&g_G[(size_t)row * NPAD + lane * 4] =
            make_float4(vr[r][0], vr[r][1], vr[r][2], vr[r][3]);
    }
    // fused transpose: Gt[n][k] bf16, k = row0+warp*4 .. +3 (4 consecutive k)
    #pragma unroll
    for (int c = 0; c < 4; c++) {
        uint2 w;
        w.x = pack_bf16x2(vr[0][c], vr[1][c]);
        w.y = pack_bf16x2(vr[2][c], vr[3][c]);
        *(uint2*)&g_Gt[(size_t)(lane * 4 + c) * N_NODES + row0 + warp * 4] = w;
    }
}

// ---------------- 4) bf16 mma.sync m16n8k16 GEMM: P = Abf @ G ----------------
// CTA 64x128, KT=32, 3 stages, 8 warps (grid 2x4), warp tile 32x32.
// Small CTA (46KB smem, ~65 regs) -> NATURAL 3-4 CTA/SM residency, 256 CTAs = 1 wave.
// Fragments via ldmatrix (A x4, B x2) -> ~2x fewer issued loads in the mainloop.
#define MTILE     64
#define KT        32
#define STAGES    3
#define A_STRIDE_H 40                       // bf16 units; row stride 80B
#define B_STRIDE  20                        // float units; row stride 80B
#define SMA_BYTES (MTILE * A_STRIDE_H * 2)  // 5120
#define SMB_BYTES (128 * B_STRIDE * 4)      // 10240
#define STAGE_BYTES (SMA_BYTES + SMB_BYTES) // 15360
#define GEMM_SMEM   (STAGES * STAGE_BYTES)  // 46080

__device__ __forceinline__ void load_stage(uint32_t sb, int buf, int tid,
                                           const __nv_bfloat16* Ab, const __nv_bfloat16* Bb, int kt) {
    uint32_t sA = sb + buf * STAGE_BYTES;
    uint32_t sB = sA + SMA_BYTES;
    const __nv_bfloat16* Ag = Ab + kt * KT;
    const __nv_bfloat16* Bg = Bb + (size_t)kt * KT;
    {   // A: 256 x 16B chunks (64 rows x 4)
        int r = tid >> 2, c = tid & 3;
        cp16(sA + r * (A_STRIDE_H * 2) + c * 16, Ag + (size_t)r * N_NODES + c * 8);
    }
    #pragma unroll
    for (int p = 0; p < 2; p++) {           // B: 512 x 16B chunks, n-major
        int ci = tid + p * 256;
        int n = ci & 127, c = ci >> 7;
        cp16(sB + n * (B_STRIDE * 4) + c * 16, Bg + (size_t)n * N_NODES + c * 8);
    }
    asm volatile("cp.async.commit_group;" ::: "memory");
}

__global__ __launch_bounds__(256) void gemm_mma() {
    extern __shared__ char smem[];
    const uint32_t sb = smem_u32(smem);
    const int tid  = threadIdx.x;
    const int warp = tid >> 5, lane = tid & 31;
    const int wr = warp >> 2, wc = warp & 3;        // warp grid 2x4
    const int r4 = lane >> 2, c4 = lane & 3;

    const int    row0 = blockIdx.x * MTILE;
    const size_t k0   = (size_t)blockIdx.y * (N_NODES / KSPLIT);
    const __nv_bfloat16* Ab = g_Abf + (size_t)row0 * N_NODES + k0;
    const __nv_bfloat16* Bb = g_Gt + k0;
    const int NT = (N_NODES / KSPLIT) / KT;         // 128

    // per-lane ldmatrix row offsets (bytes)
    const uint32_t a_lane = (uint32_t)((lane & 15) * A_STRIDE_H + ((lane & 16) ? 8 : 0)) * 2;
    const uint32_t b_lane = (uint32_t)((lane & 7) * B_STRIDE + ((lane & 8) ? 4 : 0)) * 4;

    float acc[2][4][4];
    #pragma unroll
    for (int i = 0; i < 2; i++)
        #pragma unroll
        for (int j = 0; j < 4; j++)
            #pragma unroll
            for (int q = 0; q < 4; q++) acc[i][j][q] = 0.f;

    #pragma unroll
    for (int s = 0; s < STAGES; s++) load_stage(sb, s, tid, Ab, Bb, s);

    for (int kt = 0; kt < NT; kt++) {
        asm volatile("cp.async.wait_group 2;" ::: "memory");
        __syncthreads();

        const int buf = kt % STAGES;
        const uint32_t sA = sb + buf * STAGE_BYTES;
        const uint32_t sB = sA + SMA_BYTES;

        #pragma unroll
        for (int k16 = 0; k16 < 2; k16++) {
            uint32_t a[2][4], b[4][2];
            #pragma unroll
            for (int i = 0; i < 2; i++) {
                uint32_t addr = sA + (uint32_t)((wr * 32 + i * 16) * A_STRIDE_H + k16 * 16) * 2 + a_lane;
                asm volatile("ldmatrix.sync.aligned.m8n8.x4.shared.b16 {%0,%1,%2,%3}, [%4];"
                             : "=r"(a[i][0]), "=r"(a[i][1]), "=r"(a[i][2]), "=r"(a[i][3])
                             : "r"(addr));
            }
            #pragma unroll
            for (int j = 0; j < 4; j++) {
                uint32_t addr = sB + (uint32_t)((wc * 32 + j * 8) * B_STRIDE + k16 * 8) * 4 + b_lane;
                asm volatile("ldmatrix.sync.aligned.m8n8.x2.shared.b16 {%0,%1}, [%2];"
                             : "=r"(b[j][0]), "=r"(b[j][1])
                             : "r"(addr));
            }
            #pragma unroll
            for (int i = 0; i < 2; i++)
                #pragma unroll
                for (int j = 0; j < 4; j++)
                    asm volatile(
                        "mma.sync.aligned.m16n8k16.row.col.f32.bf16.bf16.f32 "
                        "{%0,%1,%2,%3}, {%4,%5,%6,%7}, {%8,%9}, {%0,%1,%2,%3};"
                        : "+f"(acc[i][j][0]), "+f"(acc[i][j][1]),
                          "+f"(acc[i][j][2]), "+f"(acc[i][j][3])
                        : "r"(a[i][0]), "r"(a[i][1]), "r"(a[i][2]), "r"(a[i][3]),
                          "r"(b[j][0]), "r"(b[j][1]));
        }
        __syncthreads();

        if (kt + STAGES < NT)
            load_stage(sb, (kt + STAGES) % STAGES, tid, Ab, Bb, kt + STAGES);
        else
            asm volatile("cp.async.commit_group;" ::: "memory");
    }

    float* P = g_P + ((size_t)blockIdx.y * N_NODES + row0) * NPAD;
    #pragma unroll
    for (int i = 0; i < 2; i++) {
        int r = wr * 32 + i * 16 + r4;
        #pragma unroll
        for (int j = 0; j < 4; j++) {
            int c = wc * 32 + j * 8 + 2 * c4;
            *(float2*)(P + (size_t)r * NPAD + c)       = make_float2(acc[i][j][0], acc[i][j][1]);
            *(float2*)(P + (size_t)(r + 8) * NPAD + c) = make_float2(acc[i][j][2], acc[i][j][3]);
        }
    }
}

// ---------------- 5) epilogue ----------------
__global__ void epi_kernel(const float* __restrict__ b, float* __restrict__ out) {
    int idx = blockIdx.x * 256 + threadIdx.x;
    int i = idx >> 7, o = idx & 127;
    if (o < F_OUT) {
        const size_t S = (size_t)N_NODES * NPAD;
        float s = g_P[idx] + g_P[idx + S] + g_G[idx];          // split-K + exact I-term
        float v = fmaf(rsqrtf(g_colsum[i]), s, b[o]);
        out[(size_t)i * F_OUT + o] = fmaxf(v, 0.f);
    }
}

// ---------------- launch ----------------
extern "C" void kernel_launch(void* const* d_in, const int* in_sizes, int n_in,
                              void* d_out, int out_size) {
    const float *A = nullptr, *h0 = nullptr, *W = nullptr, *b = nullptr;
    for (int i = 0; i < n_in; i++) {
        switch (in_sizes[i]) {
            case N_NODES * N_NODES: A  = (const float*)d_in[i]; break;
            case N_NODES * F_IN:    h0 = (const float*)d_in[i]; break;
            case F_OUT * F_IN:      W  = (const float*)d_in[i]; break;
            case F_OUT:             b  = (const float*)d_in[i]; break;
        }
    }
    float* out = (float*)d_out;

    cudaFuncSetAttribute(gemm_mma, cudaFuncAttributeMaxDynamicSharedMemorySize, GEMM_SMEM);
    cudaFuncSetAttribute(g_kernel, cudaFuncAttributeMaxDynamicSharedMemorySize, G_SMEM);

    colsum_cvt_kernel<<<dim3(N_NODES / 4 / 256, RSPLIT), 256>>>(A);
    colsum_fin_kernel<<<N_NODES / 256, 256>>>();
    wt_kernel<<<(F_IN * NPAD + 255) / 256, 256>>>(W);
    g_kernel<<<N_NODES / G_ROWS, G_THREADS, G_SMEM>>>(h0);
    gemm_mma<<<dim3(N_NODES / MTILE, KSPLIT), 256, GEMM_SMEM>>>();
    epi_kernel<<<(N_NODES * NPAD) / 256, 256>>>(b, out);
}

// round 15
// speedup vs baseline: 1.3390x; 1.3390x over previous
#include <cuda_runtime.h>
#include <cuda_bf16.h>
#include <cstdint>

#define N_NODES 8192
#define F_IN    200
#define F_OUT   100
#define NPAD    128
#define KSPLIT  2
#define RSPLIT  32

// ---------------- scratch (no allocations allowed) ----------------
__device__ __align__(16) float g_colsum_part[RSPLIT * N_NODES];
__device__ __align__(16) float g_colsum[N_NODES];
__device__ __align__(16) float g_Wt[F_IN * NPAD];                        // [F_IN][NPAD]
__device__ __align__(16) float g_G [(size_t)N_NODES * NPAD];             // diag(dinv) h0 W^T (fp32)
__device__ __align__(16) __nv_bfloat16 g_Gt[(size_t)NPAD * N_NODES];     // bf16, [n][k]
__device__ __align__(16) __nv_bfloat16 g_Abf[(size_t)N_NODES * N_NODES]; // bf16 copy of A
__device__ __align__(16) float g_P [(size_t)KSPLIT * N_NODES * NPAD];    // split-K partials

// ================= helpers =================
__device__ __forceinline__ uint32_t smem_u32(const void* p) {
    uint32_t a;
    asm("{ .reg .u64 t; cvta.to.shared.u64 t, %1; cvt.u32.u64 %0, t; }" : "=r"(a) : "l"(p));
    return a;
}
__device__ __forceinline__ void cp16(uint32_t s, const void* g) {
    asm volatile("cp.async.cg.shared.global [%0], [%1], 16;" :: "r"(s), "l"(g) : "memory");
}
// pack two fp32 -> bf16x2 (lo = first/lower element), round-to-nearest
__device__ __forceinline__ uint32_t pack_bf16x2(float lo, float hi) {
    uint32_t r;
    asm("cvt.rn.bf16x2.f32 %0, %1, %2;" : "=r"(r) : "f"(hi), "f"(lo));
    return r;
}

// ------- 1) column sums of A + fused bf16 conversion of A (one 256MB read) -------
__global__ void colsum_cvt_kernel(const float* __restrict__ A) {
    int j4 = blockIdx.x * 256 + threadIdx.x;          // float4 column index 0..2047
    int i0 = blockIdx.y * (N_NODES / RSPLIT);
    const float4* p = (const float4*)(A + (size_t)i0 * N_NODES) + j4;
    __nv_bfloat16* dst = g_Abf + (size_t)i0 * N_NODES + j4 * 4;
    float4 s = make_float4(0.f, 0.f, 0.f, 0.f);
    #pragma unroll 4
    for (int i = 0; i < N_NODES / RSPLIT; i++) {
        float4 v = p[(size_t)i * (N_NODES / 4)];
        s.x += v.x; s.y += v.y; s.z += v.z; s.w += v.w;
        uint2 w;
        w.x = pack_bf16x2(v.x, v.y);
        w.y = pack_bf16x2(v.z, v.w);
        *(uint2*)(dst + (size_t)i * N_NODES) = w;
    }
    *(float4*)&g_colsum_part[blockIdx.y * N_NODES + j4 * 4] = s;
}
__global__ void colsum_fin_kernel() {
    int j = blockIdx.x * 256 + threadIdx.x;
    float s = 1.0f;
    #pragma unroll
    for (int p = 0; p < RSPLIT; p++) s += g_colsum_part[p * N_NODES + j];
    g_colsum[j] = s;
}

// ---------------- 2) W -> Wt (zero-padded to NPAD cols) ----------------
__global__ void wt_kernel(const float* __restrict__ W) {
    int idx = blockIdx.x * 256 + threadIdx.x;
    if (idx < F_IN * NPAD) {
        int f = idx >> 7, o = idx & 127;
        g_Wt[idx] = (o < F_OUT) ? W[o * F_IN + f] : 0.f;
    }
}

// ------- 3) G = diag(dinv) h0 @ Wt, fused transpose-to-bf16 (writes G and Gt) ----
#define G_ROWS    64
#define G_THREADS 512
#define G_SMEM    ((F_IN * NPAD + G_ROWS * F_IN) * 4)   // 153600 B
__global__ __launch_bounds__(G_THREADS, 1) void g_kernel(const float* __restrict__ h0) {
    extern __shared__ float gsm[];
    float* Wts = gsm;                       // [F_IN][NPAD]
    float* h0s = gsm + F_IN * NPAD;         // [G_ROWS][F_IN]
    const int t = threadIdx.x, warp = t >> 5, lane = t & 31;
    const int row0 = blockIdx.x * G_ROWS;

    for (int q = t; q < F_IN * NPAD / 4; q += G_THREADS)
        *(float4*)&Wts[q * 4] = *(const float4*)&g_Wt[q * 4];
    for (int q = t; q < G_ROWS * F_IN / 4; q += G_THREADS)
        *(float4*)&h0s[q * 4] = *(const float4*)&h0[(size_t)row0 * F_IN + q * 4];
    __syncthreads();

    unsigned long long acc2[4][2];
    #pragma unroll
    for (int r = 0; r < 4; r++) { acc2[r][0] = 0ull; acc2[r][1] = 0ull; }
    const float* hrow = h0s + (warp * 4) * F_IN;

    #pragma unroll 4
    for (int k = 0; k < F_IN; k++) {
        ulonglong2 b2 = *(const ulonglong2*)&Wts[k * NPAD + lane * 4];
        #pragma unroll
        for (int r = 0; r < 4; r++) {
            unsigned int av = __float_as_uint(hrow[r * F_IN + k]);
            unsigned long long a2;
            asm("mov.b64 %0, {%1, %1};" : "=l"(a2) : "r"(av));
            asm("fma.rn.f32x2 %0, %1, %2, %0;" : "+l"(acc2[r][0]) : "l"(a2), "l"(b2.x));
            asm("fma.rn.f32x2 %0, %1, %2, %0;" : "+l"(acc2[r][1]) : "l"(a2), "l"(b2.y));
        }
    }
    float vr[4][4];
    #pragma unroll
    for (int r = 0; r < 4; r++) {
        int row = row0 + warp * 4 + r;
        float dj = rsqrtf(g_colsum[row]);
        unsigned int l0, h0_, l1, h1;
        asm("mov.b64 {%0, %1}, %2;" : "=r"(l0), "=r"(h0_) : "l"(acc2[r][0]));
        asm("mov.b64 {%0, %1}, %2;" : "=r"(l1), "=r"(h1)  : "l"(acc2[r][1]));
        vr[r][0] = __uint_as_float(l0) * dj;  vr[r][1] = __uint_as_float(h0_) * dj;
        vr[r][2] = __uint_as_float(l1) * dj;  vr[r][3] = __uint_as_float(h1) * dj;
        *(float4*)&g_G[(size_t)row * NPAD + lane * 4] =
            make_float4(vr[r][0], vr[r][1], vr[r][2], vr[r][3]);
    }
    #pragma unroll
    for (int c = 0; c < 4; c++) {
        uint2 w;
        w.x = pack_bf16x2(vr[0][c], vr[1][c]);
        w.y = pack_bf16x2(vr[2][c], vr[3][c]);
        *(uint2*)&g_Gt[(size_t)(lane * 4 + c) * N_NODES + row0 + warp * 4] = w;
    }
}

// ---------------- 4) bf16 mma.sync m16n8k16 GEMM: P = Abf @ G ----------------
// CTA 128x128, KT=64, STAGES=4, 512 threads (warp grid 4x4, warp tile 32x32).
// ONE barrier per kt (write-stage (kt+3)%4 != read-stage kt%4), NT=64.
#define MTILE     128
#define KT        64
#define STAGES    4
#define AB_STRIDE 72                        // bf16 units = 144 B row stride
#define SMA_BYTES (128 * AB_STRIDE * 2)     // 18432
#define SMB_BYTES (128 * AB_STRIDE * 2)     // 18432
#define STAGE_BYTES (SMA_BYTES + SMB_BYTES) // 36864
#define GEMM_SMEM   (STAGES * STAGE_BYTES)  // 147456
#define GTHREADS  512

__device__ __forceinline__ void load_stage(uint32_t sb, int buf, int tid,
                                           const __nv_bfloat16* Ab, const __nv_bfloat16* Bb, int kt) {
    uint32_t sA = sb + buf * STAGE_BYTES;
    uint32_t sB = sA + SMA_BYTES;
    const __nv_bfloat16* Ag = Ab + kt * KT;
    const __nv_bfloat16* Bg = Bb + (size_t)kt * KT;
    #pragma unroll
    for (int p = 0; p < 2; p++) {           // A: 1024 x 16B chunks (128 rows x 8)
        int ci = tid + p * GTHREADS;
        int r = ci >> 3, c = ci & 7;
        cp16(sA + r * 144 + c * 16, Ag + (size_t)r * N_NODES + c * 8);
    }
    #pragma unroll
    for (int p = 0; p < 2; p++) {           // B: 1024 x 16B chunks, n-major
        int ci = tid + p * GTHREADS;
        int n = ci >> 3, c = ci & 7;
        cp16(sB + n * 144 + c * 16, Bg + (size_t)n * N_NODES + c * 8);
    }
    asm volatile("cp.async.commit_group;" ::: "memory");
}

__global__ __launch_bounds__(GTHREADS) void gemm_mma() {
    extern __shared__ char smem[];
    const uint32_t sb = smem_u32(smem);
    const int tid  = threadIdx.x;
    const int warp = tid >> 5, lane = tid & 31;
    const int wr = warp >> 2, wc = warp & 3;        // warp grid 4x4, tile 32x32
    const int r4 = lane >> 2, c4 = lane & 3;

    const int    row0 = blockIdx.x * MTILE;
    const size_t k0   = (size_t)blockIdx.y * (N_NODES / KSPLIT);
    const __nv_bfloat16* Ab = g_Abf + (size_t)row0 * N_NODES + k0;
    const __nv_bfloat16* Bb = g_Gt + k0;
    const int NT = (N_NODES / KSPLIT) / KT;         // 64

    // ldmatrix lane offset (verified mapping, R14): lanes 0-15 rows, lanes 16-31 +16B (k+8)
    const uint32_t lof = (uint32_t)(lane & 15) * 144 + ((lane & 16) ? 16u : 0u);

    float acc[2][4][4];
    #pragma unroll
    for (int i = 0; i < 2; i++)
        #pragma unroll
        for (int j = 0; j < 4; j++)
            #pragma unroll
            for (int q = 0; q < 4; q++) acc[i][j][q] = 0.f;

    #pragma unroll
    for (int s = 0; s < STAGES - 1; s++) load_stage(sb, s, tid, Ab, Bb, s);

    for (int kt = 0; kt < NT; kt++) {
        asm volatile("cp.async.wait_group 2;" ::: "memory");
        __syncthreads();                             // ONE barrier per kt

        const int buf = kt & 3;
        const uint32_t sA = sb + buf * STAGE_BYTES;
        const uint32_t sB = sA + SMA_BYTES;

        #pragma unroll
        for (int k16 = 0; k16 < 4; k16++) {
            uint32_t a[2][4], b[4][2];
            #pragma unroll
            for (int i = 0; i < 2; i++) {
                uint32_t addr = sA + (uint32_t)(wr * 32 + i * 16) * 144 + k16 * 32 + lof;
                asm volatile("ldmatrix.sync.aligned.m8n8.x4.shared.b16 {%0,%1,%2,%3}, [%4];"
                             : "=r"(a[i][0]), "=r"(a[i][1]), "=r"(a[i][2]), "=r"(a[i][3])
                             : "r"(addr));
            }
            #pragma unroll
            for (int jp = 0; jp < 2; jp++) {         // two n8-tiles per x4
                uint32_t addr = sB + (uint32_t)(wc * 32 + jp * 16) * 144 + k16 * 32 + lof;
                asm volatile("ldmatrix.sync.aligned.m8n8.x4.shared.b16 {%0,%1,%2,%3}, [%4];"
                             : "=r"(b[2*jp][0]), "=r"(b[2*jp+1][0]),
                               "=r"(b[2*jp][1]), "=r"(b[2*jp+1][1])
                             : "r"(addr));
            }
            #pragma unroll
            for (int i = 0; i < 2; i++)
                #pragma unroll
                for (int j = 0; j < 4; j++)
                    asm volatile(
                        "mma.sync.aligned.m16n8k16.row.col.f32.bf16.bf16.f32 "
                        "{%0,%1,%2,%3}, {%4,%5,%6,%7}, {%8,%9}, {%0,%1,%2,%3};"
                        : "+f"(acc[i][j][0]), "+f"(acc[i][j][1]),
                          "+f"(acc[i][j][2]), "+f"(acc[i][j][3])
                        : "r"(a[i][0]), "r"(a[i][1]), "r"(a[i][2]), "r"(a[i][3]),
                          "r"(b[j][0]), "r"(b[j][1]));
        }

        if (kt + STAGES - 1 < NT)
            load_stage(sb, (kt + STAGES - 1) & 3, tid, Ab, Bb, kt + STAGES - 1);
        else
            asm volatile("cp.async.commit_group;" ::: "memory");
    }

    float* P = g_P + ((size_t)blockIdx.y * N_NODES + row0) * NPAD;
    #pragma unroll
    for (int i = 0; i < 2; i++) {
        int r = wr * 32 + i * 16 + r4;
        #pragma unroll
        for (int j = 0; j < 4; j++) {
            int c = wc * 32 + j * 8 + 2 * c4;
            *(float2*)(P + (size_t)r * NPAD + c)       = make_float2(acc[i][j][0], acc[i][j][1]);
            *(float2*)(P + (size_t)(r + 8) * NPAD + c) = make_float2(acc[i][j][2], acc[i][j][3]);
        }
    }
}

// ---------------- 5) epilogue ----------------
__global__ void epi_kernel(const float* __restrict__ b, float* __restrict__ out) {
    int idx = blockIdx.x * 256 + threadIdx.x;
    int i = idx >> 7, o = idx & 127;
    if (o < F_OUT) {
        const size_t S = (size_t)N_NODES * NPAD;
        float s = g_P[idx] + g_P[idx + S] + g_G[idx];          // split-K + exact I-term
        float v = fmaf(rsqrtf(g_colsum[i]), s, b[o]);
        out[(size_t)i * F_OUT + o] = fmaxf(v, 0.f);
    }
}

// ---------------- launch ----------------
extern "C" void kernel_launch(void* const* d_in, const int* in_sizes, int n_in,
                              void* d_out, int out_size) {
    const float *A = nullptr, *h0 = nullptr, *W = nullptr, *b = nullptr;
    for (int i = 0; i < n_in; i++) {
        switch (in_sizes[i]) {
            case N_NODES * N_NODES: A  = (const float*)d_in[i]; break;
            case N_NODES * F_IN:    h0 = (const float*)d_in[i]; break;
            case F_OUT * F_IN:      W  = (const float*)d_in[i]; break;
            case F_OUT:             b  = (const float*)d_in[i]; break;
        }
    }
    float* out = (float*)d_out;

    cudaFuncSetAttribute(gemm_mma, cudaFuncAttributeMaxDynamicSharedMemorySize, GEMM_SMEM);
    cudaFuncSetAttribute(g_kernel, cudaFuncAttributeMaxDynamicSharedMemorySize, G_SMEM);

    colsum_cvt_kernel<<<dim3(N_NODES / 4 / 256, RSPLIT), 256>>>(A);
    colsum_fin_kernel<<<N_NODES / 256, 256>>>();
    wt_kernel<<<(F_IN * NPAD + 255) / 256, 256>>>(W);
    g_kernel<<<N_NODES / G_ROWS, G_THREADS, G_SMEM>>>(h0);
    gemm_mma<<<dim3(N_NODES / MTILE, KSPLIT), GTHREADS, GEMM_SMEM>>>();
    epi_kernel<<<(N_NODES * NPAD) / 256, 256>>>(b, out);
}